// round 3
// baseline (speedup 1.0000x reference)
#include <cuda_runtime.h>
#include <cuda_bf16.h>

#define N_NODES   10000
#define N_EDGES   640000
#define F_IN      128
#define H1        64
#define H2        32
#define N_CLASSES 16

// ---------------- scratch (device globals) ----------------------------------
__device__ float g_h1  [N_NODES * H1];   // x @ W1
__device__ float g_act1[N_NODES * H1];   // relu'd layer-1 activations
__device__ float g_h2  [N_NODES * H2];   // act1 @ W2
__device__ float g_dinv[N_NODES];
__device__ float g_colsum[H2];
__device__ int   g_cnt [N_NODES];        // in-degree (dst)
__device__ int   g_row [N_NODES];        // CSR row start
__device__ int   g_fill[N_NODES];        // scatter cursors
__device__ int   g_csr [N_EDGES];        // src indices grouped by dst

// ---------------- CSR build --------------------------------------------------

__global__ void init_kernel() {
    int t = blockIdx.x * blockDim.x + threadIdx.x;
    if (t < N_NODES) g_cnt[t] = 0;
    if (t < H2)      g_colsum[t] = 0.0f;
}

__global__ void hist_kernel(const int* __restrict__ ei) {
    int e = blockIdx.x * blockDim.x + threadIdx.x;
    if (e >= N_EDGES) return;
    atomicAdd(&g_cnt[ei[N_EDGES + e]], 1);
}

// single-block exclusive scan over g_cnt -> g_row/g_fill, plus dinv
__global__ __launch_bounds__(1024) void scan_kernel() {
    __shared__ int wsum[32];
    const int C = (N_NODES + 1023) / 1024;   // 10
    int tid  = threadIdx.x;
    int lane = tid & 31, wid = tid >> 5;
    int base = tid * C;

    int loc[C];
    int s = 0;
#pragma unroll
    for (int i = 0; i < C; i++) {
        int idx = base + i;
        int v = (idx < N_NODES) ? g_cnt[idx] : 0;
        loc[i] = s;
        s += v;
    }
    // inclusive warp scan of per-thread totals
    int inc = s;
#pragma unroll
    for (int o = 1; o < 32; o <<= 1) {
        int y = __shfl_up_sync(0xffffffffu, inc, o);
        if (lane >= o) inc += y;
    }
    if (lane == 31) wsum[wid] = inc;
    __syncthreads();
    if (wid == 0) {
        int v = wsum[lane];
        int winc = v;
#pragma unroll
        for (int o = 1; o < 32; o <<= 1) {
            int y = __shfl_up_sync(0xffffffffu, winc, o);
            if (lane >= o) winc += y;
        }
        wsum[lane] = winc - v;   // exclusive warp base
    }
    __syncthreads();

    int excl = wsum[wid] + (inc - s);
#pragma unroll
    for (int i = 0; i < C; i++) {
        int idx = base + i;
        if (idx < N_NODES) {
            int start = excl + loc[i];
            g_row[idx]  = start;
            g_fill[idx] = start;
            g_dinv[idx] = rsqrtf((float)g_cnt[idx] + 1.0f);
        }
    }
}

__global__ void scatter_kernel(const int* __restrict__ ei) {
    int e = blockIdx.x * blockDim.x + threadIdx.x;
    if (e >= N_EDGES) return;
    int src = ei[e];
    int dst = ei[N_EDGES + e];
    int pos = atomicAdd(&g_fill[dst], 1);
    g_csr[pos] = src;
}

// ---------------- GEMMs ------------------------------------------------------
// gemm1: h1 = x @ W1  [10000,128]@[128,64]
// tile 32 nodes x 64 outs, 128 threads, micro 4x4, K chunks of 64.
__global__ __launch_bounds__(128) void gemm1_kernel(const float* __restrict__ x,
                                                    const float* __restrict__ W1) {
    __shared__ float Ws[64][64];   // [k][out]  16 KB
    __shared__ float Xt[64][36];   // [k][node] 9.2 KB (padded, 16B-aligned cols)

    const int tid = threadIdx.x;
    const int tx  = tid & 15;      // out group: outs tx*4..tx*4+3
    const int ty  = tid >> 4;      // node group: nodes ty*4..ty*4+3 (0..7)
    const int node0 = blockIdx.x * 32;

    float acc[4][4];
#pragma unroll
    for (int i = 0; i < 4; i++)
#pragma unroll
        for (int j = 0; j < 4; j++) acc[i][j] = 0.0f;

    for (int kc = 0; kc < 2; kc++) {
        // W chunk: 64x64
        {
            int r  = tid >> 4;            // 0..7
            int c4 = (tid & 15) * 4;
#pragma unroll
            for (int p = 0; p < 8; p++) {
                int rr = r + p * 8;
                *(float4*)(&Ws[rr][c4]) =
                    *(const float4*)(W1 + (kc * 64 + rr) * H1 + c4);
            }
        }
        // X chunk transposed: Xt[k][node], 32 nodes x 64 k
        {
            int nl = tid & 31;
            int kq = (tid >> 5) * 4;      // 0,4,8,12
            int node = node0 + nl;
#pragma unroll
            for (int p = 0; p < 4; p++) {
                int k4 = kq + p * 16;
                float4 v = make_float4(0.f, 0.f, 0.f, 0.f);
                if (node < N_NODES)
                    v = *(const float4*)(x + node * F_IN + kc * 64 + k4);
                Xt[k4 + 0][nl] = v.x; Xt[k4 + 1][nl] = v.y;
                Xt[k4 + 2][nl] = v.z; Xt[k4 + 3][nl] = v.w;
            }
        }
        __syncthreads();

#pragma unroll 8
        for (int k = 0; k < 64; k++) {
            float4 wv = *(const float4*)(&Ws[k][tx * 4]);
            float4 xv = *(const float4*)(&Xt[k][ty * 4]);
            acc[0][0] += xv.x * wv.x; acc[0][1] += xv.x * wv.y;
            acc[0][2] += xv.x * wv.z; acc[0][3] += xv.x * wv.w;
            acc[1][0] += xv.y * wv.x; acc[1][1] += xv.y * wv.y;
            acc[1][2] += xv.y * wv.z; acc[1][3] += xv.y * wv.w;
            acc[2][0] += xv.z * wv.x; acc[2][1] += xv.z * wv.y;
            acc[2][2] += xv.z * wv.z; acc[2][3] += xv.z * wv.w;
            acc[3][0] += xv.w * wv.x; acc[3][1] += xv.w * wv.y;
            acc[3][2] += xv.w * wv.z; acc[3][3] += xv.w * wv.w;
        }
        __syncthreads();
    }

#pragma unroll
    for (int i = 0; i < 4; i++) {
        int node = node0 + ty * 4 + i;
        if (node < N_NODES)
            *(float4*)(g_h1 + node * H1 + tx * 4) =
                make_float4(acc[i][0], acc[i][1], acc[i][2], acc[i][3]);
    }
}

// gemm2: h2 = act1 @ W2  [10000,64]@[64,32]
// tile 64 nodes x 32 outs, 128 threads, micro 4x4, single K chunk.
__global__ __launch_bounds__(128) void gemm2_kernel(const float* __restrict__ W2) {
    __shared__ float Ws[64][32];   // 8 KB
    __shared__ float Xt[64][68];   // 17.4 KB

    const int tid = threadIdx.x;
    const int tx  = tid & 7;       // outs tx*4 (8x4=32)
    const int ty  = tid >> 3;      // nodes ty*4 (16x4=64)
    const int node0 = blockIdx.x * 64;

    float acc[4][4];
#pragma unroll
    for (int i = 0; i < 4; i++)
#pragma unroll
        for (int j = 0; j < 4; j++) acc[i][j] = 0.0f;

    {
        int r  = tid >> 3;         // 0..15
        int c4 = (tid & 7) * 4;
#pragma unroll
        for (int p = 0; p < 4; p++) {
            int rr = r + p * 16;
            *(float4*)(&Ws[rr][c4]) = *(const float4*)(W2 + rr * H2 + c4);
        }
    }
    {
        int nl = tid & 63;
        int kq = (tid >> 6) * 4;   // 0 or 4
        int node = node0 + nl;
#pragma unroll
        for (int p = 0; p < 8; p++) {
            int k4 = kq + p * 8;
            float4 v = make_float4(0.f, 0.f, 0.f, 0.f);
            if (node < N_NODES)
                v = *(const float4*)(g_act1 + node * H1 + k4);
            Xt[k4 + 0][nl] = v.x; Xt[k4 + 1][nl] = v.y;
            Xt[k4 + 2][nl] = v.z; Xt[k4 + 3][nl] = v.w;
        }
    }
    __syncthreads();

#pragma unroll 8
    for (int k = 0; k < 64; k++) {
        float4 wv = *(const float4*)(&Ws[k][tx * 4]);
        float4 xv = *(const float4*)(&Xt[k][ty * 4]);
        acc[0][0] += xv.x * wv.x; acc[0][1] += xv.x * wv.y;
        acc[0][2] += xv.x * wv.z; acc[0][3] += xv.x * wv.w;
        acc[1][0] += xv.y * wv.x; acc[1][1] += xv.y * wv.y;
        acc[1][2] += xv.y * wv.z; acc[1][3] += xv.y * wv.w;
        acc[2][0] += xv.z * wv.x; acc[2][1] += xv.z * wv.y;
        acc[2][2] += xv.z * wv.z; acc[2][3] += xv.z * wv.w;
        acc[3][0] += xv.w * wv.x; acc[3][1] += xv.w * wv.y;
        acc[3][2] += xv.w * wv.z; acc[3][3] += xv.w * wv.w;
    }

#pragma unroll
    for (int i = 0; i < 4; i++) {
        int node = node0 + ty * 4 + i;
        if (node < N_NODES)
            *(float4*)(g_h2 + node * H2 + tx * 4) =
                make_float4(acc[i][0], acc[i][1], acc[i][2], acc[i][3]);
    }
}

// ---------------- fused CSR aggregation --------------------------------------
// layer 1: warp per node, lane handles 2 feats; fused bias+self-loop+relu.
__global__ void agg1_kernel(const float* __restrict__ b1) {
    int gw   = (blockIdx.x * blockDim.x + threadIdx.x) >> 5;  // node
    int lane = threadIdx.x & 31;
    if (gw >= N_NODES) return;

    int start = g_row[gw];
    int deg   = g_cnt[gw];
    const float2* __restrict__ H = (const float2*)g_h1;

    float ax = 0.f, ay = 0.f;
    for (int j0 = 0; j0 < deg; j0 += 32) {
        int jj = j0 + lane;
        int idx = 0; float cs = 0.f;
        if (jj < deg) { idx = g_csr[start + jj]; cs = __ldg(&g_dinv[idx]); }
        int m = min(32, deg - j0);
#pragma unroll 4
        for (int t = 0; t < m; t++) {
            int   s = __shfl_sync(0xffffffffu, idx, t);
            float c = __shfl_sync(0xffffffffu, cs,  t);
            float2 v = H[s * 32 + lane];
            ax += c * v.x;
            ay += c * v.y;
        }
    }
    float d  = g_dinv[gw];
    float dd = d * d;
    float2 h = H[gw * 32 + lane];
    float2 r;
    r.x = fmaxf(ax * d + h.x * dd + __ldg(&b1[lane * 2 + 0]), 0.f);
    r.y = fmaxf(ay * d + h.y * dd + __ldg(&b1[lane * 2 + 1]), 0.f);
    ((float2*)g_act1)[gw * 32 + lane] = r;
}

// layer 2: warp per node, lane = feature; fused epilogue + mean-pool colsum.
__global__ void agg2_kernel(const float* __restrict__ b2) {
    __shared__ float sred[8][33];
    int gw   = (blockIdx.x * blockDim.x + threadIdx.x) >> 5;
    int lane = threadIdx.x & 31;
    int wloc = threadIdx.x >> 5;

    float r = 0.f;
    if (gw < N_NODES) {
        int start = g_row[gw];
        int deg   = g_cnt[gw];
        float acc = 0.f;
        for (int j0 = 0; j0 < deg; j0 += 32) {
            int jj = j0 + lane;
            int idx = 0; float cs = 0.f;
            if (jj < deg) { idx = g_csr[start + jj]; cs = __ldg(&g_dinv[idx]); }
            int m = min(32, deg - j0);
#pragma unroll 4
            for (int t = 0; t < m; t++) {
                int   s = __shfl_sync(0xffffffffu, idx, t);
                float c = __shfl_sync(0xffffffffu, cs,  t);
                acc += c * g_h2[s * 32 + lane];
            }
        }
        float d = g_dinv[gw];
        r = fmaxf(acc * d + g_h2[gw * 32 + lane] * (d * d) + __ldg(&b2[lane]), 0.f);
    }
    sred[wloc][lane] = r;
    __syncthreads();
    if (wloc == 0) {
        float v = sred[0][lane];
#pragma unroll
        for (int w = 1; w < 8; w++) v += sred[w][lane];
        atomicAdd(&g_colsum[lane], v);
    }
}

// out = (colsum / N) @ Wfc + bfc
__global__ void final_kernel(const float* __restrict__ Wfc,
                             const float* __restrict__ bfc,
                             float* __restrict__ out) {
    int c = threadIdx.x;
    if (c >= N_CLASSES) return;
    float acc = bfc[c];
    const float inv_n = 1.0f / (float)N_NODES;
#pragma unroll
    for (int f = 0; f < H2; f++)
        acc += (g_colsum[f] * inv_n) * Wfc[f * N_CLASSES + c];
    out[c] = acc;
}

// ---------------- launch ------------------------------------------------------
extern "C" void kernel_launch(void* const* d_in, const int* in_sizes, int n_in,
                              void* d_out, int out_size) {
    const float* x   = (const float*)d_in[0];
    const float* W1  = (const float*)d_in[1];
    const float* b1  = (const float*)d_in[2];
    const float* W2  = (const float*)d_in[3];
    const float* b2  = (const float*)d_in[4];
    const float* Wfc = (const float*)d_in[5];
    const float* bfc = (const float*)d_in[6];
    const int*   ei  = (const int*)  d_in[7];
    float* out = (float*)d_out;

    init_kernel<<<40, 256>>>();
    hist_kernel<<<N_EDGES / 256, 256>>>(ei);
    scan_kernel<<<1, 1024>>>();
    scatter_kernel<<<N_EDGES / 256, 256>>>(ei);

    gemm1_kernel<<<(N_NODES + 31) / 32, 128>>>(x, W1);     // 313 blocks
    agg1_kernel<<<N_NODES * 32 / 256, 256>>>(b1);          // 1250 blocks

    gemm2_kernel<<<(N_NODES + 63) / 64, 128>>>(W2);        // 157 blocks
    agg2_kernel<<<N_NODES * 32 / 256, 256>>>(b2);          // 1250 blocks

    final_kernel<<<1, 32>>>(Wfc, bfc, out);
}

// round 4
// speedup vs baseline: 1.0216x; 1.0216x over previous
#include <cuda_runtime.h>
#include <cuda_bf16.h>

#define N_NODES   10000
#define N_EDGES   640000
#define F_IN      128
#define H1        64
#define H2        32
#define N_CLASSES 16

// ---------------- scratch (device globals) ----------------------------------
__device__ float g_h1  [N_NODES * H1];    // x @ W1
__device__ float g_act1[N_NODES * H1];    // relu'd layer-1 activations
__device__ float g_h2  [N_NODES * H2];    // act1 @ W2
__device__ float g_dinv[N_NODES];
__device__ float g_colsum[H2];
__device__ int   g_cnt [N_NODES];         // in-degree; ALWAYS zero at launch start
__device__ int   g_row [N_NODES + 1];     // CSR row start (+ sentinel)
__device__ int   g_rank[N_EDGES];         // per-edge rank within its dst bucket
__device__ int   g_csr [N_EDGES];         // src indices grouped by dst
__device__ float g_coef[N_EDGES];         // dinv[src]*dinv[dst] grouped by dst

// ---------------- CSR build --------------------------------------------------

// pass1: histogram AND per-edge rank in one atomic pass
__global__ void pass1_kernel(const int* __restrict__ ei) {
    int e = blockIdx.x * blockDim.x + threadIdx.x;
    if (e >= N_EDGES) return;
    g_rank[e] = atomicAdd(&g_cnt[ei[N_EDGES + e]], 1);
}

// single-block exclusive scan over g_cnt -> g_row, dinv; then RESET cnt to 0
// (keeps the "cnt is zero at launch entry" invariant across graph replays)
__global__ __launch_bounds__(1024) void scan_kernel() {
    __shared__ int wsum[32];
    const int C = (N_NODES + 1023) / 1024;   // 10
    int tid  = threadIdx.x;
    int lane = tid & 31, wid = tid >> 5;
    int base = tid * C;

    int loc[C];
    int cnt[C];
    int s = 0;
#pragma unroll
    for (int i = 0; i < C; i++) {
        int idx = base + i;
        int v = (idx < N_NODES) ? g_cnt[idx] : 0;
        cnt[i] = v;
        loc[i] = s;
        s += v;
    }
    int inc = s;
#pragma unroll
    for (int o = 1; o < 32; o <<= 1) {
        int y = __shfl_up_sync(0xffffffffu, inc, o);
        if (lane >= o) inc += y;
    }
    if (lane == 31) wsum[wid] = inc;
    __syncthreads();
    if (wid == 0) {
        int v = wsum[lane];
        int winc = v;
#pragma unroll
        for (int o = 1; o < 32; o <<= 1) {
            int y = __shfl_up_sync(0xffffffffu, winc, o);
            if (lane >= o) winc += y;
        }
        wsum[lane] = winc - v;
    }
    __syncthreads();

    int excl = wsum[wid] + (inc - s);
#pragma unroll
    for (int i = 0; i < C; i++) {
        int idx = base + i;
        if (idx < N_NODES) {
            g_row[idx]  = excl + loc[i];
            g_dinv[idx] = rsqrtf((float)cnt[i] + 1.0f);
            g_cnt[idx]  = 0;                 // reset for next launch/replay
        }
    }
    if (tid == 0) g_row[N_NODES] = N_EDGES;  // sentinel
    if (tid < H2) g_colsum[tid] = 0.0f;      // zero mean-pool accumulator
}

// pass2: place edges (no atomics) and precompute coefficients
__global__ void pass2_kernel(const int* __restrict__ ei) {
    int e = blockIdx.x * blockDim.x + threadIdx.x;
    if (e >= N_EDGES) return;
    int src = ei[e];
    int dst = ei[N_EDGES + e];
    int pos = g_row[dst] + g_rank[e];
    g_csr [pos] = src;
    g_coef[pos] = g_dinv[src] * g_dinv[dst];
}

// ---------------- GEMMs ------------------------------------------------------
// gemm1: h1 = x @ W1  [10000,128]@[128,64]; 32 nodes x 64 outs, micro 4x4.
__global__ __launch_bounds__(128) void gemm1_kernel(const float* __restrict__ x,
                                                    const float* __restrict__ W1) {
    __shared__ float Ws[64][64];
    __shared__ float Xt[64][36];

    const int tid = threadIdx.x;
    const int tx  = tid & 15;
    const int ty  = tid >> 4;
    const int node0 = blockIdx.x * 32;

    float acc[4][4];
#pragma unroll
    for (int i = 0; i < 4; i++)
#pragma unroll
        for (int j = 0; j < 4; j++) acc[i][j] = 0.0f;

    for (int kc = 0; kc < 2; kc++) {
        {
            int r  = tid >> 4;
            int c4 = (tid & 15) * 4;
#pragma unroll
            for (int p = 0; p < 8; p++) {
                int rr = r + p * 8;
                *(float4*)(&Ws[rr][c4]) =
                    *(const float4*)(W1 + (kc * 64 + rr) * H1 + c4);
            }
        }
        {
            int nl = tid & 31;
            int kq = (tid >> 5) * 4;
            int node = node0 + nl;
#pragma unroll
            for (int p = 0; p < 4; p++) {
                int k4 = kq + p * 16;
                float4 v = make_float4(0.f, 0.f, 0.f, 0.f);
                if (node < N_NODES)
                    v = *(const float4*)(x + node * F_IN + kc * 64 + k4);
                Xt[k4 + 0][nl] = v.x; Xt[k4 + 1][nl] = v.y;
                Xt[k4 + 2][nl] = v.z; Xt[k4 + 3][nl] = v.w;
            }
        }
        __syncthreads();

#pragma unroll 8
        for (int k = 0; k < 64; k++) {
            float4 wv = *(const float4*)(&Ws[k][tx * 4]);
            float4 xv = *(const float4*)(&Xt[k][ty * 4]);
            acc[0][0] += xv.x * wv.x; acc[0][1] += xv.x * wv.y;
            acc[0][2] += xv.x * wv.z; acc[0][3] += xv.x * wv.w;
            acc[1][0] += xv.y * wv.x; acc[1][1] += xv.y * wv.y;
            acc[1][2] += xv.y * wv.z; acc[1][3] += xv.y * wv.w;
            acc[2][0] += xv.z * wv.x; acc[2][1] += xv.z * wv.y;
            acc[2][2] += xv.z * wv.z; acc[2][3] += xv.z * wv.w;
            acc[3][0] += xv.w * wv.x; acc[3][1] += xv.w * wv.y;
            acc[3][2] += xv.w * wv.z; acc[3][3] += xv.w * wv.w;
        }
        __syncthreads();
    }

#pragma unroll
    for (int i = 0; i < 4; i++) {
        int node = node0 + ty * 4 + i;
        if (node < N_NODES)
            *(float4*)(g_h1 + node * H1 + tx * 4) =
                make_float4(acc[i][0], acc[i][1], acc[i][2], acc[i][3]);
    }
}

// gemm2: h2 = act1 @ W2  [10000,64]@[64,32]; 64 nodes x 32 outs, micro 4x4.
__global__ __launch_bounds__(128) void gemm2_kernel(const float* __restrict__ W2) {
    __shared__ float Ws[64][32];
    __shared__ float Xt[64][68];

    const int tid = threadIdx.x;
    const int tx  = tid & 7;
    const int ty  = tid >> 3;
    const int node0 = blockIdx.x * 64;

    float acc[4][4];
#pragma unroll
    for (int i = 0; i < 4; i++)
#pragma unroll
        for (int j = 0; j < 4; j++) acc[i][j] = 0.0f;

    {
        int r  = tid >> 3;
        int c4 = (tid & 7) * 4;
#pragma unroll
        for (int p = 0; p < 4; p++) {
            int rr = r + p * 16;
            *(float4*)(&Ws[rr][c4]) = *(const float4*)(W2 + rr * H2 + c4);
        }
    }
    {
        int nl = tid & 63;
        int kq = (tid >> 6) * 4;
        int node = node0 + nl;
#pragma unroll
        for (int p = 0; p < 8; p++) {
            int k4 = kq + p * 8;
            float4 v = make_float4(0.f, 0.f, 0.f, 0.f);
            if (node < N_NODES)
                v = *(const float4*)(g_act1 + node * H1 + k4);
            Xt[k4 + 0][nl] = v.x; Xt[k4 + 1][nl] = v.y;
            Xt[k4 + 2][nl] = v.z; Xt[k4 + 3][nl] = v.w;
        }
    }
    __syncthreads();

#pragma unroll 8
    for (int k = 0; k < 64; k++) {
        float4 wv = *(const float4*)(&Ws[k][tx * 4]);
        float4 xv = *(const float4*)(&Xt[k][ty * 4]);
        acc[0][0] += xv.x * wv.x; acc[0][1] += xv.x * wv.y;
        acc[0][2] += xv.x * wv.z; acc[0][3] += xv.x * wv.w;
        acc[1][0] += xv.y * wv.x; acc[1][1] += xv.y * wv.y;
        acc[1][2] += xv.y * wv.z; acc[1][3] += xv.y * wv.w;
        acc[2][0] += xv.z * wv.x; acc[2][1] += xv.z * wv.y;
        acc[2][2] += xv.z * wv.z; acc[2][3] += xv.z * wv.w;
        acc[3][0] += xv.w * wv.x; acc[3][1] += xv.w * wv.y;
        acc[3][2] += xv.w * wv.z; acc[3][3] += xv.w * wv.w;
    }

#pragma unroll
    for (int i = 0; i < 4; i++) {
        int node = node0 + ty * 4 + i;
        if (node < N_NODES)
            *(float4*)(g_h2 + node * H2 + tx * 4) =
                make_float4(acc[i][0], acc[i][1], acc[i][2], acc[i][3]);
    }
}

// ---------------- fused CSR aggregation --------------------------------------
// layer 1: warp per node, lane handles 2 feats; fused bias+self-loop+relu.
__global__ void agg1_kernel(const float* __restrict__ b1) {
    int gw   = (blockIdx.x * blockDim.x + threadIdx.x) >> 5;
    int lane = threadIdx.x & 31;
    if (gw >= N_NODES) return;

    int start = g_row[gw];
    int deg   = g_row[gw + 1] - start;
    const float2* __restrict__ H = (const float2*)g_h1;

    float ax = 0.f, ay = 0.f;
    for (int j0 = 0; j0 < deg; j0 += 32) {
        int jj = j0 + lane;
        int idx = 0; float cf = 0.f;
        if (jj < deg) { idx = g_csr[start + jj]; cf = g_coef[start + jj]; }
        int m = min(32, deg - j0);
#pragma unroll 4
        for (int t = 0; t < m; t++) {
            int   s = __shfl_sync(0xffffffffu, idx, t);
            float c = __shfl_sync(0xffffffffu, cf,  t);
            float2 v = H[s * 32 + lane];
            ax += c * v.x;
            ay += c * v.y;
        }
    }
    float d  = g_dinv[gw];
    float dd = d * d;
    float2 h = H[gw * 32 + lane];
    float2 r;
    r.x = fmaxf(ax + h.x * dd + __ldg(&b1[lane * 2 + 0]), 0.f);
    r.y = fmaxf(ay + h.y * dd + __ldg(&b1[lane * 2 + 1]), 0.f);
    ((float2*)g_act1)[gw * 32 + lane] = r;
}

// layer 2: warp per node, lane = feature; fused epilogue + mean-pool colsum.
__global__ void agg2_kernel(const float* __restrict__ b2) {
    __shared__ float sred[8][33];
    int gw   = (blockIdx.x * blockDim.x + threadIdx.x) >> 5;
    int lane = threadIdx.x & 31;
    int wloc = threadIdx.x >> 5;

    float r = 0.f;
    if (gw < N_NODES) {
        int start = g_row[gw];
        int deg   = g_row[gw + 1] - start;
        float acc = 0.f;
        for (int j0 = 0; j0 < deg; j0 += 32) {
            int jj = j0 + lane;
            int idx = 0; float cf = 0.f;
            if (jj < deg) { idx = g_csr[start + jj]; cf = g_coef[start + jj]; }
            int m = min(32, deg - j0);
#pragma unroll 4
            for (int t = 0; t < m; t++) {
                int   s = __shfl_sync(0xffffffffu, idx, t);
                float c = __shfl_sync(0xffffffffu, cf,  t);
                acc += c * g_h2[s * 32 + lane];
            }
        }
        float d = g_dinv[gw];
        r = fmaxf(acc + g_h2[gw * 32 + lane] * (d * d) + __ldg(&b2[lane]), 0.f);
    }
    sred[wloc][lane] = r;
    __syncthreads();
    if (wloc == 0) {
        float v = sred[0][lane];
#pragma unroll
        for (int w = 1; w < 8; w++) v += sred[w][lane];
        atomicAdd(&g_colsum[lane], v);
    }
}

// out = (colsum / N) @ Wfc + bfc
__global__ void final_kernel(const float* __restrict__ Wfc,
                             const float* __restrict__ bfc,
                             float* __restrict__ out) {
    int c = threadIdx.x;
    if (c >= N_CLASSES) return;
    float acc = bfc[c];
    const float inv_n = 1.0f / (float)N_NODES;
#pragma unroll
    for (int f = 0; f < H2; f++)
        acc += (g_colsum[f] * inv_n) * Wfc[f * N_CLASSES + c];
    out[c] = acc;
}

// ---------------- launch ------------------------------------------------------
extern "C" void kernel_launch(void* const* d_in, const int* in_sizes, int n_in,
                              void* d_out, int out_size) {
    const float* x   = (const float*)d_in[0];
    const float* W1  = (const float*)d_in[1];
    const float* b1  = (const float*)d_in[2];
    const float* W2  = (const float*)d_in[3];
    const float* b2  = (const float*)d_in[4];
    const float* Wfc = (const float*)d_in[5];
    const float* bfc = (const float*)d_in[6];
    const int*   ei  = (const int*)  d_in[7];
    float* out = (float*)d_out;

    pass1_kernel<<<N_EDGES / 256, 256>>>(ei);
    scan_kernel<<<1, 1024>>>();
    pass2_kernel<<<N_EDGES / 256, 256>>>(ei);

    gemm1_kernel<<<(N_NODES + 31) / 32, 128>>>(x, W1);
    agg1_kernel<<<N_NODES * 32 / 256, 256>>>(b1);

    gemm2_kernel<<<(N_NODES + 63) / 64, 128>>>(W2);
    agg2_kernel<<<N_NODES * 32 / 256, 256>>>(b2);

    final_kernel<<<1, 32>>>(Wfc, bfc, out);
}

// round 5
// speedup vs baseline: 1.1825x; 1.1576x over previous
#include <cuda_runtime.h>
#include <cuda_bf16.h>

#define N_NODES   10000
#define N_EDGES   640000
#define F_IN      128
#define H1        64
#define H2        32
#define N_CLASSES 16

// ---------------- scratch (device globals) ----------------------------------
__device__ float g_h1  [N_NODES * H1];   // x @ W1
__device__ float g_agg1[N_NODES * H1];   // init h1*d^2+b1, then += neighbor agg
__device__ float g_h2  [N_NODES * H2];   // relu(agg1) @ W2
__device__ float g_agg2[N_NODES * H2];   // init h2*d^2+b2, then += neighbor agg
__device__ int   g_deg [N_NODES];        // ALWAYS zero at launch entry
__device__ float g_dinv[N_NODES];
__device__ float g_colsum[H2];

// vectorized L2 reduction (no return), sm_90+
__device__ __forceinline__ void red_add_v4(float4* addr, float4 v) {
    asm volatile("red.global.add.v4.f32 [%0], {%1,%2,%3,%4};"
                 :: "l"(addr), "f"(v.x), "f"(v.y), "f"(v.z), "f"(v.w)
                 : "memory");
}

// ---------------- degree -----------------------------------------------------
__global__ void hist_kernel(const int* __restrict__ ei) {
    int e = blockIdx.x * blockDim.x + threadIdx.x;
    if (e >= N_EDGES) return;
    atomicAdd(&g_deg[ei[N_EDGES + e]], 1);   // no-return -> RED
}

__global__ void dinv_kernel() {
    int n = blockIdx.x * blockDim.x + threadIdx.x;
    if (n < N_NODES) {
        g_dinv[n] = rsqrtf((float)g_deg[n] + 1.0f);
        g_deg[n]  = 0;                        // reset for next replay
    }
    if (n < H2) g_colsum[n] = 0.0f;
}

// ---------------- gemm1: h1 = x @ W1, agg1 = h1*d^2 + b1 ---------------------
// tile 32 nodes x 64 outs, 128 threads, micro 4x4, full K resident in smem.
__global__ __launch_bounds__(128) void gemm1_kernel(const float* __restrict__ x,
                                                    const float* __restrict__ W1,
                                                    const float* __restrict__ b1) {
    __shared__ float Ws[128][64];  // 32 KB
    __shared__ float Xt[128][36];  // 18.4 KB

    const int tid = threadIdx.x;
    const int tx  = tid & 15;      // out group (x4)
    const int ty  = tid >> 4;      // node group (x4)
    const int node0 = blockIdx.x * 32;

    // load W1 full: 128x64, 64 floats per thread
    {
        int r  = tid >> 4;             // 0..7
        int c4 = (tid & 15) * 4;
#pragma unroll
        for (int p = 0; p < 16; p++) {
            int rr = r + p * 8;
            *(float4*)(&Ws[rr][c4]) = *(const float4*)(W1 + rr * H1 + c4);
        }
    }
    // load X transposed: 32 nodes x 128 k
    {
        int nl = tid & 31;
        int kq = (tid >> 5) * 4;       // 0,4,8,12
        int node = node0 + nl;
#pragma unroll
        for (int p = 0; p < 8; p++) {
            int k4 = kq + p * 16;
            float4 v = make_float4(0.f, 0.f, 0.f, 0.f);
            if (node < N_NODES)
                v = *(const float4*)(x + node * F_IN + k4);
            Xt[k4 + 0][nl] = v.x; Xt[k4 + 1][nl] = v.y;
            Xt[k4 + 2][nl] = v.z; Xt[k4 + 3][nl] = v.w;
        }
    }
    __syncthreads();

    float acc[4][4];
#pragma unroll
    for (int i = 0; i < 4; i++)
#pragma unroll
        for (int j = 0; j < 4; j++) acc[i][j] = 0.0f;

#pragma unroll 8
    for (int k = 0; k < 128; k++) {
        float4 wv = *(const float4*)(&Ws[k][tx * 4]);
        float4 xv = *(const float4*)(&Xt[k][ty * 4]);
        acc[0][0] += xv.x * wv.x; acc[0][1] += xv.x * wv.y;
        acc[0][2] += xv.x * wv.z; acc[0][3] += xv.x * wv.w;
        acc[1][0] += xv.y * wv.x; acc[1][1] += xv.y * wv.y;
        acc[1][2] += xv.y * wv.z; acc[1][3] += xv.y * wv.w;
        acc[2][0] += xv.z * wv.x; acc[2][1] += xv.z * wv.y;
        acc[2][2] += xv.z * wv.z; acc[2][3] += xv.z * wv.w;
        acc[3][0] += xv.w * wv.x; acc[3][1] += xv.w * wv.y;
        acc[3][2] += xv.w * wv.z; acc[3][3] += xv.w * wv.w;
    }

    float4 bv = *(const float4*)(b1 + tx * 4);
#pragma unroll
    for (int i = 0; i < 4; i++) {
        int node = node0 + ty * 4 + i;
        if (node < N_NODES) {
            float d  = g_dinv[node];
            float dd = d * d;
            float4 h = make_float4(acc[i][0], acc[i][1], acc[i][2], acc[i][3]);
            *(float4*)(g_h1 + node * H1 + tx * 4) = h;
            float4 a = make_float4(h.x * dd + bv.x, h.y * dd + bv.y,
                                   h.z * dd + bv.z, h.w * dd + bv.w);
            *(float4*)(g_agg1 + node * H1 + tx * 4) = a;
        }
    }
}

// ---------------- edge aggregation layer 1 (red-atomic) ----------------------
// 16 threads per edge, float4 each (64 feats)
__global__ void agg1_kernel(const int* __restrict__ ei) {
    long long t = (long long)blockIdx.x * blockDim.x + threadIdx.x;
    int e = (int)(t >> 4);
    int q = (int)(t & 15);
    if (e >= N_EDGES) return;
    int src = __ldg(&ei[e]);
    int dst = __ldg(&ei[N_EDGES + e]);
    float c = __ldg(&g_dinv[src]) * __ldg(&g_dinv[dst]);
    float4 v = ((const float4*)g_h1)[src * 16 + q];
    v.x *= c; v.y *= c; v.z *= c; v.w *= c;
    red_add_v4(&((float4*)g_agg1)[dst * 16 + q], v);
}

// ---------------- gemm2: h2 = relu(agg1) @ W2, agg2 = h2*d^2 + b2 ------------
// tile 64 nodes x 32 outs, 128 threads, micro 4x4. relu fused into X load.
__global__ __launch_bounds__(128) void gemm2_kernel(const float* __restrict__ W2,
                                                    const float* __restrict__ b2) {
    __shared__ float Ws[64][32];
    __shared__ float Xt[64][68];

    const int tid = threadIdx.x;
    const int tx  = tid & 7;
    const int ty  = tid >> 3;
    const int node0 = blockIdx.x * 64;

    {
        int r  = tid >> 3;
        int c4 = (tid & 7) * 4;
#pragma unroll
        for (int p = 0; p < 4; p++) {
            int rr = r + p * 16;
            *(float4*)(&Ws[rr][c4]) = *(const float4*)(W2 + rr * H2 + c4);
        }
    }
    {
        int nl = tid & 63;
        int kq = (tid >> 6) * 4;
        int node = node0 + nl;
#pragma unroll
        for (int p = 0; p < 8; p++) {
            int k4 = kq + p * 8;
            float4 v = make_float4(0.f, 0.f, 0.f, 0.f);
            if (node < N_NODES)
                v = *(const float4*)(g_agg1 + node * H1 + k4);
            Xt[k4 + 0][nl] = fmaxf(v.x, 0.f); Xt[k4 + 1][nl] = fmaxf(v.y, 0.f);
            Xt[k4 + 2][nl] = fmaxf(v.z, 0.f); Xt[k4 + 3][nl] = fmaxf(v.w, 0.f);
        }
    }
    __syncthreads();

    float acc[4][4];
#pragma unroll
    for (int i = 0; i < 4; i++)
#pragma unroll
        for (int j = 0; j < 4; j++) acc[i][j] = 0.0f;

#pragma unroll 8
    for (int k = 0; k < 64; k++) {
        float4 wv = *(const float4*)(&Ws[k][tx * 4]);
        float4 xv = *(const float4*)(&Xt[k][ty * 4]);
        acc[0][0] += xv.x * wv.x; acc[0][1] += xv.x * wv.y;
        acc[0][2] += xv.x * wv.z; acc[0][3] += xv.x * wv.w;
        acc[1][0] += xv.y * wv.x; acc[1][1] += xv.y * wv.y;
        acc[1][2] += xv.y * wv.z; acc[1][3] += xv.y * wv.w;
        acc[2][0] += xv.z * wv.x; acc[2][1] += xv.z * wv.y;
        acc[2][2] += xv.z * wv.z; acc[2][3] += xv.z * wv.w;
        acc[3][0] += xv.w * wv.x; acc[3][1] += xv.w * wv.y;
        acc[3][2] += xv.w * wv.z; acc[3][3] += xv.w * wv.w;
    }

    float4 bv = *(const float4*)(b2 + tx * 4);
#pragma unroll
    for (int i = 0; i < 4; i++) {
        int node = node0 + ty * 4 + i;
        if (node < N_NODES) {
            float d  = g_dinv[node];
            float dd = d * d;
            float4 h = make_float4(acc[i][0], acc[i][1], acc[i][2], acc[i][3]);
            *(float4*)(g_h2 + node * H2 + tx * 4) = h;
            float4 a = make_float4(h.x * dd + bv.x, h.y * dd + bv.y,
                                   h.z * dd + bv.z, h.w * dd + bv.w);
            *(float4*)(g_agg2 + node * H2 + tx * 4) = a;
        }
    }
}

// ---------------- edge aggregation layer 2 (red-atomic) ----------------------
// 8 threads per edge, float4 each (32 feats)
__global__ void agg2_kernel(const int* __restrict__ ei) {
    long long t = (long long)blockIdx.x * blockDim.x + threadIdx.x;
    int e = (int)(t >> 3);
    int q = (int)(t & 7);
    if (e >= N_EDGES) return;
    int src = __ldg(&ei[e]);
    int dst = __ldg(&ei[N_EDGES + e]);
    float c = __ldg(&g_dinv[src]) * __ldg(&g_dinv[dst]);
    float4 v = ((const float4*)g_h2)[src * 8 + q];
    v.x *= c; v.y *= c; v.z *= c; v.w *= c;
    red_add_v4(&((float4*)g_agg2)[dst * 8 + q], v);
}

// ---------------- layer-2 epilogue: relu + mean-pool column sums -------------
__global__ void post2_kernel() {
    __shared__ float s[256];
    int t = blockIdx.x * blockDim.x + threadIdx.x;   // over N_NODES*H2
    float v = 0.0f;
    if (t < N_NODES * H2) v = fmaxf(g_agg2[t], 0.0f);
    s[threadIdx.x] = v;
    __syncthreads();
#pragma unroll
    for (int st = 128; st >= 32; st >>= 1) {
        if (threadIdx.x < st) s[threadIdx.x] += s[threadIdx.x + st];
        __syncthreads();
    }
    if (threadIdx.x < 32) atomicAdd(&g_colsum[threadIdx.x], s[threadIdx.x]);
}

// out = (colsum / N) @ Wfc + bfc
__global__ void final_kernel(const float* __restrict__ Wfc,
                             const float* __restrict__ bfc,
                             float* __restrict__ out) {
    int c = threadIdx.x;
    if (c >= N_CLASSES) return;
    float acc = bfc[c];
    const float inv_n = 1.0f / (float)N_NODES;
#pragma unroll
    for (int f = 0; f < H2; f++)
        acc += (g_colsum[f] * inv_n) * Wfc[f * N_CLASSES + c];
    out[c] = acc;
}

// ---------------- launch ------------------------------------------------------
extern "C" void kernel_launch(void* const* d_in, const int* in_sizes, int n_in,
                              void* d_out, int out_size) {
    const float* x   = (const float*)d_in[0];
    const float* W1  = (const float*)d_in[1];
    const float* b1  = (const float*)d_in[2];
    const float* W2  = (const float*)d_in[3];
    const float* b2  = (const float*)d_in[4];
    const float* Wfc = (const float*)d_in[5];
    const float* bfc = (const float*)d_in[6];
    const int*   ei  = (const int*)  d_in[7];
    float* out = (float*)d_out;

    hist_kernel<<<N_EDGES / 256, 256>>>(ei);
    dinv_kernel<<<(N_NODES + 255) / 256, 256>>>();

    gemm1_kernel<<<(N_NODES + 31) / 32, 128>>>(x, W1, b1);
    agg1_kernel<<<N_EDGES * 16 / 256, 256>>>(ei);

    gemm2_kernel<<<(N_NODES + 63) / 64, 128>>>(W2, b2);
    agg2_kernel<<<N_EDGES * 8 / 256, 256>>>(ei);

    post2_kernel<<<(N_NODES * H2 + 255) / 256, 256>>>();
    final_kernel<<<1, 32>>>(Wfc, bfc, out);
}